// round 16
// baseline (speedup 1.0000x reference)
#include <cuda_runtime.h>
#include <cuda_fp16.h>
#include <cstdint>
#include <cstddef>

#define TLEN 4096
#define NB   32
#define HD   256
#define HS   264   // G staging: halves per n-row (256 + 8 pad)

// Scratch (device globals: allocation-free rule)
static __device__ __align__(256) float  g_Xp0[(size_t)TLEN * NB * HD]; // frag-layout preacts L0
static __device__ __align__(256) float  g_Xp1[(size_t)TLEN * NB * HD]; // frag-layout preacts L1
static __device__ __align__(256) __half g_H0h[(size_t)TLEN * NB * HD]; // L0 hidden [t][cid][k][n]
static __device__ int g_progA[4];
static __device__ int g_progB[8];   // [par*4 + cid]: pairs of that parity done
static __device__ int g_progG[8];   // [par*4 + cid]: t's of that parity done

// ---------------------------------------------------------------------------
__device__ __forceinline__ float tanh_mufu(float x) {
    float y;
    asm("tanh.approx.f32 %0, %1;" : "=f"(y) : "f"(x));
    return y;
}
__device__ __forceinline__ uint32_t pack_h2(float lo, float hi) {
    __half2 h = __floats2half2_rn(lo, hi);
    return *reinterpret_cast<uint32_t*>(&h);
}
__device__ __forceinline__ uint32_t smem_u32(const void* p) {
    uint32_t a;
    asm("{ .reg .u64 t; cvta.to.shared.u64 t, %1; cvt.u32.u64 %0, t; }" : "=r"(a) : "l"(p));
    return a;
}
__device__ __forceinline__ int ld_acq(const int* p) {
    int v;
    asm volatile("ld.acquire.gpu.global.s32 %0, [%1];" : "=r"(v) : "l"(p));
    return v;
}
__device__ __forceinline__ void st_rel(int* p, int v) {
    asm volatile("st.release.gpu.global.s32 [%0], %1;" :: "l"(p), "r"(v));
}
__device__ __forceinline__ int prewait(const int* p, int v) {
    int a;
    while ((a = ld_acq(p)) < v) { __nanosleep(200); }
    return a;
}
#define HMMA(acc, af, bf0, bf1)                                               \
    asm volatile(                                                             \
        "mma.sync.aligned.m16n8k16.row.col.f32.f16.f16.f32 "                  \
        "{%0,%1,%2,%3}, {%4,%5,%6,%7}, {%8,%9}, {%0,%1,%2,%3};"               \
        : "+f"((acc)[0]), "+f"((acc)[1]), "+f"((acc)[2]), "+f"((acc)[3])      \
        : "r"((af)[0]), "r"((af)[1]), "r"((af)[2]), "r"((af)[3]),             \
          "r"(bf0), "r"(bf1))
#define LDSM4(r0, r1, r2, r3, a)                                              \
    asm volatile("ldmatrix.sync.aligned.m8n8.x4.shared.b16 {%0,%1,%2,%3}, [%4];" \
        : "=r"(r0), "=r"(r1), "=r"(r2), "=r"(r3) : "r"(a))
#define LDSM4T(r0, r1, r2, r3, a)                                             \
    asm volatile("ldmatrix.sync.aligned.m8n8.x4.trans.shared.b16 {%0,%1,%2,%3}, [%4];" \
        : "=r"(r0), "=r"(r1), "=r"(r2), "=r"(r3) : "r"(a))

// n-major (G): 8 LDSM4 + 16 HMMA, TWO depth-8 chains.
#define MMA_STEP16_2(c0, c1, afr, ab)                                         \
    do {                                                                      \
        _Pragma("unroll")                                                     \
        for (int kk = 0; kk < 8; ++kk) {                                      \
            uint32_t b0, b1, b2, b3;                                          \
            LDSM4(b0, b1, b2, b3, (ab) + kk * 64);                            \
            HMMA((c0), (afr)[2 * kk],     b0, b1);                            \
            HMMA((c1), (afr)[2 * kk + 1], b2, b3);                            \
        }                                                                     \
    } while (0)

// k-major (B): 8 LDSM4T + 16 HMMA, TWO depth-8 chains.
#define MMA_STEP16T_2(c0, c1, afr, ab)                                        \
    do {                                                                      \
        _Pragma("unroll")                                                     \
        for (int kk = 0; kk < 8; ++kk) {                                      \
            uint32_t b0, b1, b2, b3;                                          \
            LDSM4T(b0, b1, b2, b3, (ab) + kk * 512);                          \
            HMMA((c0), (afr)[2 * kk],     b0, b1);                            \
            HMMA((c1), (afr)[2 * kk + 1], b2, b3);                            \
        }                                                                     \
    } while (0)

// k-major (A/C): 8 LDSM4T + 16 HMMA, FOUR depth-4 chains (chain = kt & 3).
#define MMA_STEP16T_4(cc, afr, ab)                                            \
    do {                                                                      \
        _Pragma("unroll")                                                     \
        for (int kk = 0; kk < 8; ++kk) {                                      \
            uint32_t b0, b1, b2, b3;                                          \
            LDSM4T(b0, b1, b2, b3, (ab) + kk * 512);                          \
            HMMA((cc)[(2 * kk) & 3],     (afr)[2 * kk],     b0, b1);          \
            HMMA((cc)[(2 * kk + 1) & 3], (afr)[2 * kk + 1], b2, b3);          \
        }                                                                     \
    } while (0)

#define SUM4C(cc, i) (((cc)[0][i] + (cc)[1][i]) + ((cc)[2][i] + (cc)[3][i]))

// Register-resident A fragments for rows (r0, r0+8) of a 256x256 fp32 weight.
__device__ __forceinline__ void load_frags16(uint32_t afr[16][4],
                                             const float* __restrict__ W,
                                             int r0, int tid4) {
    #pragma unroll
    for (int kt = 0; kt < 16; ++kt) {
        const int k0 = kt * 16 + tid4 * 2;
        const float* p0 = W + (size_t)r0 * HD + k0;
        const float* p1 = W + (size_t)(r0 + 8) * HD + k0;
        afr[kt][0] = pack_h2(p0[0], p0[1]);
        afr[kt][1] = pack_h2(p1[0], p1[1]);
        afr[kt][2] = pack_h2(p0[8], p0[9]);
        afr[kt][3] = pack_h2(p1[8], p1[9]);
    }
}

// ---------------------------------------------------------------------------
// Flag reset (flags persist across graph replays; must run before fused kernel)
__global__ void reset_flags_kernel() {
    const int t = threadIdx.x;
    if (t < 4) g_progA[t] = 0;
    if (t < 8) { g_progB[t] = 0; g_progG[t] = 0; }
}

// ---------------------------------------------------------------------------
// Fused 4-stage pipelined kernel.  grid = 24 CTAs x 512 threads (16 warps):
//   CTA 0-3  (A): layer-0 recurrence     CTA 4-11 (B): xp1 projection (t-par split)
//   CTA 12-15(C): layer-1 recurrence     CTA 16-23(G): xp0 input GEMM (t-par split)
__global__ void __launch_bounds__(512, 1) rnn_fused_kernel(
    const float* __restrict__ xin,  const float* __restrict__ Wih0,
    const float* __restrict__ Whh0, const float* __restrict__ Whh1,
    const float* __restrict__ Wih1,
    const float* __restrict__ b_ih, const float* __restrict__ b_hh,
    const float* __restrict__ h0all, float* __restrict__ Out)
{
    __shared__ __align__(16) __half hsT[2][256][8];  // scan h state (k-major)
    __shared__ __align__(16) float  obuf[2][8][260]; // C: output staging
    __shared__ __align__(16) __half xs[2][8][HS];    // G: x staging

    const int bx   = blockIdx.x;
    const int tid  = threadIdx.x;
    const int w    = tid >> 5;
    const int lane = tid & 31;
    const int grp  = lane >> 2;
    const int tid4 = lane & 3;
    const int m0   = w * 16 + grp;
    const int n0   = tid4 * 2;

    const uint32_t hs_base = smem_u32(&hsT[0][0][0]);
    const uint32_t lsmT = hs_base + (uint32_t)lane * 16;
    const uint32_t BUFB = 4096;

    // ======================= Stage A: layer-0 recurrence ====================
    if (bx < 4) {
        const int cid = bx, b0 = cid * 8;
        uint32_t afr[16][4];
        load_frags16(afr, Whh0, m0, tid4);

        for (int idx = tid; idx < 2048; idx += 512) {
            const int k = idx >> 3, n = idx & 7;
            hsT[0][k][n] = __float2half_rn(h0all[(size_t)(b0 + n) * HD + k]);
        }
        __syncthreads();

        // skid: wait for G to produce 16 t's per parity (t < 32 available)
        int avG[2];
        avG[0] = prewait(&g_progG[cid], 16);
        avG[1] = prewait(&g_progG[4 + cid], 16);

        const size_t fb = ((size_t)cid * 16 + w) * 128 + lane * 4;
        float4 xa = *(const float4*)(g_Xp0 + fb);           // x(0)
        float4 xb = *(const float4*)(g_Xp0 + 8192 + fb);    // x(1)

        for (int u = 0; u <= TLEN; ++u) {
            const int rd = u & 1, wr = rd ^ 1;

            float cc[4][4];
            #pragma unroll
            for (int j = 1; j < 4; ++j)
                #pragma unroll
                for (int i = 0; i < 4; ++i) cc[j][i] = 0.0f;
            const float* x = (const float*)&xa;
            cc[0][0] = x[0]; cc[0][1] = x[1]; cc[0][2] = x[2]; cc[0][3] = x[3];
            if (u < TLEN) MMA_STEP16T_4(cc, afr, lsmT + rd * BUFB);

            // publish h0(u-1) behind the MMA drain (flat 4KB copy)
            if (u > 0) {
                uint2 v = *(const uint2*)((const char*)&hsT[rd][0][0] + tid * 8);
                *(uint2*)((char*)g_H0h +
                          (((size_t)(u - 1) * 4 + cid) * 4096) + tid * 8) = v;
            }

            if (u < TLEN) {
                const int tn = (u + 2 < TLEN) ? u + 2 : TLEN - 1;
                const int par = tn & 1, ii = tn >> 1;
                if (avG[par] <= ii) {
                    while ((avG[par] = ld_acq(&g_progG[par * 4 + cid])) <= ii) {}
                }
                float4 xn = *(const float4*)(g_Xp0 + (size_t)tn * 8192 + fb);

                float v0 = tanh_mufu(SUM4C(cc, 0));   // (m0,   n0)
                float v1 = tanh_mufu(SUM4C(cc, 1));   // (m0,   n0+1)
                float v2 = tanh_mufu(SUM4C(cc, 2));   // (m0+8, n0)
                float v3 = tanh_mufu(SUM4C(cc, 3));   // (m0+8, n0+1)
                *(uint32_t*)&hsT[wr][m0][n0]     = pack_h2(v0, v1);
                *(uint32_t*)&hsT[wr][m0 + 8][n0] = pack_h2(v2, v3);
                xa = xb; xb = xn;
            }
            __syncthreads();
            if (tid == 0 && u > 0 && ((u & 3) == 0 || u == TLEN))
                st_rel(&g_progA[cid], u);
        }
    }
    // ======================= Stage B: xp1 projection (t-parity split) =======
    else if (bx < 12) {
        const int j = bx - 4, par = j >> 2, cid = j & 3;
        uint32_t afr[16][4];
        load_frags16(afr, Wih1, m0, tid4);
        const float bias_lo = b_ih[HD + m0] + b_hh[HD + m0];
        const float bias_hi = b_ih[HD + m0 + 8] + b_hh[HD + m0 + 8];

        int avA = 0;
        if (tid == 0) avA = prewait(&g_progA[cid], 32);

        for (int pidx = 0; pidx < 1024; ++pidx) {
            const int tp = 4 * pidx + 2 * par;
            if (tid == 0 && avA < tp + 2) {
                while ((avA = ld_acq(&g_progA[cid])) < tp + 2) {}
            }
            __syncthreads();

            // stage two h0 tiles (flat 4KB copies)
            uint2 v0 = *(const uint2*)((const char*)g_H0h +
                        (((size_t)tp * 4 + cid) * 4096) + tid * 8);
            uint2 v1 = *(const uint2*)((const char*)g_H0h +
                        (((size_t)(tp + 1) * 4 + cid) * 4096) + tid * 8);
            *(uint2*)((char*)&hsT[0][0][0] + tid * 8) = v0;
            *(uint2*)((char*)&hsT[0][0][0] + 4096 + tid * 8) = v1;
            __syncthreads();

            #pragma unroll
            for (int s = 0; s < 2; ++s) {
                float c0[4], c1[4] = {};
                c0[0] = bias_lo; c0[1] = bias_lo; c0[2] = bias_hi; c0[3] = bias_hi;
                MMA_STEP16T_2(c0, c1, afr, lsmT + s * BUFB);
                float4 o;
                o.x = c0[0] + c1[0];
                o.y = c0[1] + c1[1];
                o.z = c0[2] + c1[2];
                o.w = c0[3] + c1[3];
                *(float4*)(g_Xp1 +
                    (((size_t)(tp + s) * 4 + cid) * 16 + w) * 128 + lane * 4) = o;
            }
            __syncthreads();
            if (tid == 0 && (((pidx + 1) & 3) == 0 || pidx == 1023))
                st_rel(&g_progB[par * 4 + cid], pidx + 1);
        }
    }
    // ======================= Stage C: layer-1 recurrence ====================
    else if (bx < 16) {
        const int cid = bx - 12, b0 = cid * 8;
        uint32_t afr[16][4];
        load_frags16(afr, Whh1, m0, tid4);

        const float* h0l1 = h0all + (size_t)NB * HD;
        for (int idx = tid; idx < 2048; idx += 512) {
            const int k = idx >> 3, n = idx & 7;
            hsT[0][k][n] = __float2half_rn(h0l1[(size_t)(b0 + n) * HD + k]);
        }
        __syncthreads();

        // skid: 16 pairs per parity = 64 t's available
        int avB[2];
        avB[0] = prewait(&g_progB[cid], 16);
        avB[1] = prewait(&g_progB[4 + cid], 16);

        const size_t fb = ((size_t)cid * 16 + w) * 128 + lane * 4;
        float4 xa = *(const float4*)(g_Xp1 + fb);
        float4 xb = *(const float4*)(g_Xp1 + 8192 + fb);

        for (int u = 0; u <= TLEN; ++u) {
            const int rd = u & 1, wr = rd ^ 1;

            float cc[4][4];
            #pragma unroll
            for (int j = 1; j < 4; ++j)
                #pragma unroll
                for (int i = 0; i < 4; ++i) cc[j][i] = 0.0f;
            const float* x = (const float*)&xa;
            cc[0][0] = x[0]; cc[0][1] = x[1]; cc[0][2] = x[2]; cc[0][3] = x[3];
            if (u < TLEN) MMA_STEP16T_4(cc, afr, lsmT + rd * BUFB);

            // flush Out(u-1) behind the MMA drain (float4 per thread)
            if (u > 0) {
                const int fn = tid >> 6, fc = (tid & 63) * 4;
                float4 a = *(const float4*)&obuf[rd][fn][fc];
                *(float4*)(Out + ((size_t)(u - 1) * NB + b0 + fn) * HD + fc) = a;
            }

            if (u < TLEN) {
                const int tn = (u + 2 < TLEN) ? u + 2 : TLEN - 1;
                const int p = tn >> 1, par = p & 1, need = (p >> 1) + 1;
                if (avB[par] < need) {
                    while ((avB[par] = ld_acq(&g_progB[par * 4 + cid])) < need) {}
                }
                float4 xn = *(const float4*)(g_Xp1 + (size_t)tn * 8192 + fb);

                float v0 = tanh_mufu(SUM4C(cc, 0));
                float v1 = tanh_mufu(SUM4C(cc, 1));
                float v2 = tanh_mufu(SUM4C(cc, 2));
                float v3 = tanh_mufu(SUM4C(cc, 3));
                *(uint32_t*)&hsT[wr][m0][n0]     = pack_h2(v0, v1);
                *(uint32_t*)&hsT[wr][m0 + 8][n0] = pack_h2(v2, v3);
                obuf[wr][n0][m0]         = v0;
                obuf[wr][n0 + 1][m0]     = v1;
                obuf[wr][n0][m0 + 8]     = v2;
                obuf[wr][n0 + 1][m0 + 8] = v3;
                xa = xb; xb = xn;
            }
            __syncthreads();
        }
    }
    // ======================= Stage G: xp0 input GEMM ========================
    else {
        const int j    = bx - 16;      // 0..7
        const int gcid = j & 3;
        const int par  = j >> 2;       // t parity this CTA produces

        uint32_t afr[16][4];
        load_frags16(afr, Wih0, m0, tid4);
        const float bias_lo = b_ih[m0] + b_hh[m0];
        const float bias_hi = b_ih[m0 + 8] + b_hh[m0 + 8];

        const uint32_t xs_base = smem_u32(&xs[0][0][0]);
        const uint32_t lsm = xs_base + (uint32_t)(lane & 7) * (HS * 2)
                                     + (uint32_t)(lane >> 3) * 16;
        const uint32_t XBUF = 8 * HS * 2;

        const int sn = tid >> 7, sk = (tid & 127) * 2;   // rows {sn, sn+4}
        int tile = par * 4 + gcid;                       // t = par

        {
            float2 a0 = *(const float2*)&xin[((size_t)tile * 8 + sn) * HD + sk];
            float2 a1 = *(const float2*)&xin[((size_t)tile * 8 + sn + 4) * HD + sk];
            *(uint32_t*)&xs[0][sn][sk]     = pack_h2(a0.x, a0.y);
            *(uint32_t*)&xs[0][sn + 4][sk] = pack_h2(a1.x, a1.y);
        }
        __syncthreads();

        for (int it = 0; it < 2048; ++it) {
            const int cur = it & 1, nxt = cur ^ 1;

            float2 a0, a1;
            if (it + 1 < 2048) {
                const size_t nb = ((size_t)(tile + 8) * 8 + sn) * HD + sk;
                a0 = *(const float2*)&xin[nb];
                a1 = *(const float2*)&xin[nb + 4 * HD];
            }

            float c0[4], c1[4] = {};
            c0[0] = bias_lo; c0[1] = bias_lo; c0[2] = bias_hi; c0[3] = bias_hi;
            MMA_STEP16_2(c0, c1, afr, lsm + cur * XBUF);

            if (it + 1 < 2048) {
                *(uint32_t*)&xs[nxt][sn][sk]     = pack_h2(a0.x, a0.y);
                *(uint32_t*)&xs[nxt][sn + 4][sk] = pack_h2(a1.x, a1.y);
            }

            float4 o;
            o.x = c0[0] + c1[0];
            o.y = c0[1] + c1[1];
            o.z = c0[2] + c1[2];
            o.w = c0[3] + c1[3];
            *(float4*)(g_Xp0 + ((size_t)tile * 16 + w) * 128 + lane * 4) = o;
            __syncthreads();
            if (tid == 0 && (((it + 1) & 3) == 0 || it + 1 == 2048))
                st_rel(&g_progG[par * 4 + gcid], it + 1);
            tile += 8;   // next t of this parity
        }
    }
}

// -------------------------------- launcher ----------------------------------
extern "C" void kernel_launch(void* const* d_in, const int* in_sizes, int n_in,
                              void* d_out, int out_size) {
    const float* x    = (const float*)d_in[0];  // [T,B,D]
    const float* W_ih = (const float*)d_in[1];  // [L,H,D]
    const float* W_hh = (const float*)d_in[2];  // [L,H,H]
    const float* b_ih = (const float*)d_in[3];  // [L,H]
    const float* b_hh = (const float*)d_in[4];  // [L,H]
    const float* h0   = (const float*)d_in[5];  // [L,B,H]
    float* out = (float*)d_out;                 // [T,B,H]

    reset_flags_kernel<<<1, 32>>>();
    rnn_fused_kernel<<<24, 512>>>(x, W_ih,
                                  W_hh, W_hh + HD * HD, W_ih + HD * HD,
                                  b_ih, b_hh, h0, out);
}